// round 7
// baseline (speedup 1.0000x reference)
#include <cuda_runtime.h>
#include <math.h>

// Problem capacities (from reference: N=100000, E=1600000)
#define NMAX 100000
#define EMAX 1600000

// ---------------- scratch (device globals; no allocation allowed) ----------------
__device__ __align__(16) float g_buf0[NMAX * 64];
__device__ __align__(16) float g_buf1[NMAX * 64];
__device__ __align__(16) float g_buf2[NMAX * 64];
__device__ int   g_deg[NMAX];
__device__ float g_dinv[NMAX];
__device__ __align__(16) int4 g_edge[EMAX];   // {src, dst, bitcast(norm), pad}
__device__ int   g_edsel;                     // 1 = edge_index is int64, 0 = int32

// ---------------- edge dtype detection (deterministic, one block) ----------------
// For int64 indices (< 2^31), odd 32-bit words are always 0 (high halves).
// For int32 indices, odd words are random node ids in [0, N) -> ~never 0.
__global__ void k_detect(const unsigned int* __restrict__ w) {
    __shared__ int cnt;
    if (threadIdx.x == 0) cnt = 0;
    __syncthreads();
    int z = 0;
    for (int i = threadIdx.x; i < 512; i += blockDim.x)
        if (w[2 * i + 1] == 0u) z++;
    atomicAdd(&cnt, z);
    __syncthreads();
    if (threadIdx.x == 0) g_edsel = (cnt > 480) ? 1 : 0;
}

// ---------------- degree / normalization precompute ----------------
__global__ void k_initdeg(int n) {
    int i = blockIdx.x * blockDim.x + threadIdx.x;
    if (i < n) g_deg[i] = 1;  // self loop
}

__global__ void k_edgeprep(const void* __restrict__ ei, int E, int n) {
    int e = blockIdx.x * blockDim.x + threadIdx.x;
    if (e >= E) return;
    int s, d;
    if (g_edsel) {
        const long long* p = (const long long*)ei;
        s = (int)__ldg(&p[e]);
        d = (int)__ldg(&p[(long)E + e]);
    } else {
        const int* p = (const int*)ei;
        s = __ldg(&p[e]);
        d = __ldg(&p[(long)E + e]);
    }
    // Defense: clamp into [0, n). No-op for valid indices; prevents IMA,
    // turning any residual decode bug into a measurable wrong answer.
    if ((unsigned)s >= (unsigned)n) s = 0;
    if ((unsigned)d >= (unsigned)n) d = 0;
    g_edge[e].x = s;
    g_edge[e].y = d;
    atomicAdd(&g_deg[d], 1);
}

__global__ void k_dinv(int n) {
    int i = blockIdx.x * blockDim.x + threadIdx.x;
    if (i < n) g_dinv[i] = rsqrtf((float)g_deg[i]);
}

__global__ void k_enorm(int E) {
    int e = blockIdx.x * blockDim.x + threadIdx.x;
    if (e >= E) return;
    int4 rec = g_edge[e];
    float w = g_dinv[rec.x] * g_dinv[rec.y];
    g_edge[e].z = __float_as_int(w);
}

// ---------------- GEMM with fused pre-op and fused self-loop epilogue ----------------
// C[n,FOUT] = preop(A)[n,FIN] @ W[FIN,FOUT] (+bias_out)
//   PRE:  preop(a)_k = relu(a_k + prebias_k)   (bias+relu of PREVIOUS conv, fused)
//   SELF: also write C2[r] = C[r] * dinv[r]^2  (self-loop term of CURRENT conv)
// Block: 64 rows x FOUT cols. Threads (FOUT/4, 16); each thread -> 4x4 micro-tile.
template<int FIN, int FOUT, bool PRE, bool SELF>
__global__ void k_gemm(const float* __restrict__ A, const float* __restrict__ W,
                       const float* __restrict__ bias_out,
                       const float* __restrict__ prebias,
                       float* __restrict__ C, float* __restrict__ C2, int n) {
    __shared__ __align__(16) float Ws[FIN * FOUT];
    __shared__ __align__(16) float Pb[PRE ? FIN : 4];
    const int nthr = blockDim.x * blockDim.y;
    int tid = threadIdx.y * blockDim.x + threadIdx.x;
    for (int i = tid; i < FIN * FOUT / 4; i += nthr)
        ((float4*)Ws)[i] = ((const float4*)W)[i];
    if (PRE) {
        for (int i = tid; i < FIN; i += nthr) Pb[i] = prebias[i];
    }
    __syncthreads();

    const int tx = threadIdx.x;           // col group: cols [tx*4, tx*4+4)
    const int ty = threadIdx.y;           // row group
    const int row0 = blockIdx.x * 64 + ty * 4;

    const float4* A4  = (const float4*)A;
    const float4* Ws4 = (const float4*)Ws;

    int r[4];
#pragma unroll
    for (int i = 0; i < 4; i++) {
        int rr = row0 + i;
        r[i] = (rr < n) ? rr : (n - 1);   // clamp for loads; stores masked below
    }

    float acc[4][4] = {};
#pragma unroll 4
    for (int k4 = 0; k4 < FIN / 4; k4++) {
        float4 pb;
        if (PRE) pb = ((const float4*)Pb)[k4];
        float4 a[4];
#pragma unroll
        for (int i = 0; i < 4; i++) {
            a[i] = __ldg(A4 + (long)r[i] * (FIN / 4) + k4);
            if (PRE) {
                a[i].x = fmaxf(a[i].x + pb.x, 0.f);
                a[i].y = fmaxf(a[i].y + pb.y, 0.f);
                a[i].z = fmaxf(a[i].z + pb.z, 0.f);
                a[i].w = fmaxf(a[i].w + pb.w, 0.f);
            }
        }
#pragma unroll
        for (int kk = 0; kk < 4; kk++) {
            float4 w = Ws4[(k4 * 4 + kk) * (FOUT / 4) + tx];
#pragma unroll
            for (int i = 0; i < 4; i++) {
                float av = (kk == 0) ? a[i].x : (kk == 1) ? a[i].y : (kk == 2) ? a[i].z : a[i].w;
                acc[i][0] += av * w.x;
                acc[i][1] += av * w.y;
                acc[i][2] += av * w.z;
                acc[i][3] += av * w.w;
            }
        }
    }

    float4 bv = make_float4(0.f, 0.f, 0.f, 0.f);
    if (bias_out) bv = ((const float4*)bias_out)[tx];
#pragma unroll
    for (int i = 0; i < 4; i++) {
        int rr = row0 + i;
        if (rr < n) {
            float4 o = make_float4(acc[i][0] + bv.x, acc[i][1] + bv.y,
                                   acc[i][2] + bv.z, acc[i][3] + bv.w);
            ((float4*)C)[(long)rr * (FOUT / 4) + tx] = o;
            if (SELF) {
                float s = g_dinv[rr];
                s = s * s;
                float4 o2 = make_float4(o.x * s, o.y * s, o.z * s, o.w * s);
                ((float4*)C2)[(long)rr * (FOUT / 4) + tx] = o2;
            }
        }
    }
}

// ---------------- edge scatter: out[dst] += hW[src] * enorm, vector atomics ----------------
template<int F>
__global__ void k_scatter(const float4* __restrict__ hw, float* __restrict__ out, int E) {
    const int TPE = F / 4;  // threads (float4 lanes) per edge
    long gid = (long)blockIdx.x * blockDim.x + threadIdx.x;
    int e = (int)(gid / TPE);
    if (e >= E) return;
    int l = (int)(gid % TPE);
    int4 rec = __ldg(&g_edge[e]);        // one 16B load: {src, dst, norm, pad}
    int s = rec.x;
    int d = rec.y;
    float w = __int_as_float(rec.z);
    float4 v = __ldg(hw + (long)s * TPE + l);
    float* p = out + (long)d * F + (l << 2);
    asm volatile("red.global.add.v4.f32 [%0], {%1,%2,%3,%4};"
                 :: "l"(p), "f"(v.x * w), "f"(v.y * w), "f"(v.z * w), "f"(v.w * w)
                 : "memory");
}

// ---------------- final: add bias, L2-normalize each 32-wide row ----------------
// NOTE: called with agg == out (in place). No __restrict__ on these two:
// each thread reads its own element before writing it, and we must not let
// the compiler assume no aliasing.
__global__ void k_final(const float* agg, const float* __restrict__ bias,
                        float* out, int n) {
    int gtid = blockIdx.x * blockDim.x + threadIdx.x;
    int row = gtid >> 5;
    int lane = gtid & 31;
    if (row >= n) return;
    float v = agg[(long)row * 32 + lane] + __ldg(&bias[lane]);
    float ss = v * v;
#pragma unroll
    for (int o = 16; o; o >>= 1) ss += __shfl_xor_sync(0xFFFFFFFFu, ss, o);
    float nrm = sqrtf(ss);
    out[(long)row * 32 + lane] = v / fmaxf(nrm, 1e-12f);
}

// ---------------- launch ----------------
extern "C" void kernel_launch(void* const* d_in, const int* in_sizes, int n_in,
                              void* d_out, int out_size) {
    const float* x    = (const float*)d_in[0];
    const void*  ei   = d_in[1];
    const float* Wpre = (const float*)d_in[2];
    const float* bpre = (const float*)d_in[3];
    const float* W1   = (const float*)d_in[4];
    const float* b1   = (const float*)d_in[5];
    const float* W2   = (const float*)d_in[6];
    const float* b2   = (const float*)d_in[7];
    const float* W3   = (const float*)d_in[8];
    const float* b3   = (const float*)d_in[9];

    int n = in_sizes[0] / 128;
    int E = in_sizes[1] / 2;

    float *buf0, *buf1, *buf2;
    cudaGetSymbolAddress((void**)&buf0, g_buf0);
    cudaGetSymbolAddress((void**)&buf1, g_buf1);
    cudaGetSymbolAddress((void**)&buf2, g_buf2);
    float* outp = (float*)d_out;

    const int T = 256;
    int nb_n = (n + T - 1) / T;
    int nb_e = (E + T - 1) / T;
    long sc64 = (long)E * 16;
    long sc32 = (long)E * 8;
    int nb_s64 = (int)((sc64 + T - 1) / T);
    int nb_s32 = (int)((sc32 + T - 1) / T);
    int nb_gem = (n + 63) / 64;

    // edge dtype detection + graph normalization precompute
    k_detect<<<1, 256>>>((const unsigned int*)ei);
    k_initdeg<<<nb_n, T>>>(n);
    k_edgeprep<<<nb_e, T>>>(ei, E, n);
    k_dinv<<<nb_n, T>>>(n);
    k_enorm<<<nb_e, T>>>(E);

    // linear_pre: buf0 = x @ W_pre + b_pre
    k_gemm<128, 64, false, false><<<nb_gem, dim3(16, 16)>>>(
        x, Wpre, bpre, nullptr, buf0, nullptr, n);

    // conv1: hW1 = buf0 @ W1 -> buf1; self term -> buf2; scatter edges into buf2
    k_gemm<64, 64, false, true><<<nb_gem, dim3(16, 16)>>>(
        buf0, W1, nullptr, nullptr, buf1, buf2, n);
    k_scatter<64><<<nb_s64, T>>>((const float4*)buf1, buf2, E);

    // conv2: reads agg1 (buf2) with fused relu(+b1); hW2 -> buf0; self -> buf1; scatter -> buf1
    k_gemm<64, 64, true, true><<<nb_gem, dim3(16, 16)>>>(
        buf2, W2, nullptr, b1, buf0, buf1, n);
    k_scatter<64><<<nb_s64, T>>>((const float4*)buf0, buf1, E);

    // conv3: reads agg2 (buf1) with fused relu(+b2); hW3 -> buf2; self -> d_out; scatter -> d_out
    k_gemm<64, 32, true, true><<<nb_gem, dim3(8, 16)>>>(
        buf1, W3, nullptr, b2, buf2, outp, n);
    k_scatter<32><<<nb_s32, T>>>((const float4*)buf2, outp, E);

    // final: bias + L2 normalize, in place on d_out
    k_final<<<(n * 32 + T - 1) / T, T>>>(outp, b3, outp, n);
}

// round 14
// speedup vs baseline: 1.3315x; 1.3315x over previous
#include <cuda_runtime.h>
#include <math.h>

// Problem capacities (from reference: N=100000, E=1600000)
#define NMAX 100000
#define EMAX 1600000
#define SCAN_TILE 1024

// ---------------- scratch (device globals; no allocation allowed) ----------------
__device__ __align__(16) float g_buf0[NMAX * 64];
__device__ __align__(16) float g_buf1[NMAX * 64];
__device__ __align__(16) float g_buf2[NMAX * 64];
__device__ int   g_deg[NMAX];        // 1 + in-degree (self loop included)
__device__ float g_dinv[NMAX];
__device__ __align__(8) int2 g_edge2[EMAX];  // decoded {src, dst}
__device__ __align__(8) int2 g_csr[EMAX];    // dst-bucketed {src, bitcast(norm)}
__device__ int   g_rowstart[NMAX];   // CSR start offsets (real edges only)
__device__ int   g_cursor[NMAX];     // fill cursors
__device__ int   g_blocksum[128];
__device__ int   g_edsel;            // 1 = edge_index is int64, 0 = int32

// ---------------- edge dtype detection (deterministic, one block) ----------------
// For int64 indices (< 2^31), odd 32-bit words are always 0 (high halves).
// For int32 indices, odd words are random node ids in [0, N) -> ~never 0.
__global__ void k_detect(const unsigned int* __restrict__ w) {
    __shared__ int cnt;
    if (threadIdx.x == 0) cnt = 0;
    __syncthreads();
    int z = 0;
    for (int i = threadIdx.x; i < 512; i += blockDim.x)
        if (w[2 * i + 1] == 0u) z++;
    atomicAdd(&cnt, z);
    __syncthreads();
    if (threadIdx.x == 0) g_edsel = (cnt > 480) ? 1 : 0;
}

// ---------------- degree / normalization precompute ----------------
__global__ void k_initdeg(int n) {
    int i = blockIdx.x * blockDim.x + threadIdx.x;
    if (i < n) g_deg[i] = 1;  // self loop
}

__global__ void k_edgeprep(const void* __restrict__ ei, int E, int n) {
    int e = blockIdx.x * blockDim.x + threadIdx.x;
    if (e >= E) return;
    int s, d;
    if (g_edsel) {
        const long long* p = (const long long*)ei;
        s = (int)__ldg(&p[e]);
        d = (int)__ldg(&p[(long)E + e]);
    } else {
        const int* p = (const int*)ei;
        s = __ldg(&p[e]);
        d = __ldg(&p[(long)E + e]);
    }
    if ((unsigned)s >= (unsigned)n) s = 0;   // defense: clamp, no-op for valid data
    if ((unsigned)d >= (unsigned)n) d = 0;
    g_edge2[e] = make_int2(s, d);
    atomicAdd(&g_deg[d], 1);
}

__global__ void k_dinv(int n) {
    int i = blockIdx.x * blockDim.x + threadIdx.x;
    if (i < n) g_dinv[i] = rsqrtf((float)g_deg[i]);
}

// ---------------- prefix-sum of (deg-1) -> CSR row starts ----------------
__global__ void k_scan1(int n) {
    __shared__ int sh[SCAN_TILE];
    int i = blockIdx.x * SCAN_TILE + threadIdx.x;
    int v = (i < n) ? (g_deg[i] - 1) : 0;   // real in-edges only
    sh[threadIdx.x] = v;
    __syncthreads();
    for (int o = 1; o < SCAN_TILE; o <<= 1) {
        int t = (threadIdx.x >= o) ? sh[threadIdx.x - o] : 0;
        __syncthreads();
        sh[threadIdx.x] += t;
        __syncthreads();
    }
    if (i < n) g_rowstart[i] = sh[threadIdx.x] - v;       // within-block exclusive
    if (threadIdx.x == SCAN_TILE - 1) g_blocksum[blockIdx.x] = sh[SCAN_TILE - 1];
}

__global__ void k_scan2(int nb) {
    __shared__ int sh[128];
    int v = (threadIdx.x < nb) ? g_blocksum[threadIdx.x] : 0;
    sh[threadIdx.x] = v;
    __syncthreads();
    for (int o = 1; o < 128; o <<= 1) {
        int t = (threadIdx.x >= o) ? sh[threadIdx.x - o] : 0;
        __syncthreads();
        sh[threadIdx.x] += t;
        __syncthreads();
    }
    if (threadIdx.x < nb) g_blocksum[threadIdx.x] = sh[threadIdx.x] - v;  // exclusive
}

__global__ void k_scan3(int n) {
    int i = blockIdx.x * blockDim.x + threadIdx.x;
    if (i >= n) return;
    int st = g_rowstart[i] + g_blocksum[i / SCAN_TILE];
    g_rowstart[i] = st;
    g_cursor[i] = st;
}

// ---------------- fill CSR buckets: {src, norm} sorted by dst ----------------
__global__ void k_fill(int E) {
    int e = blockIdx.x * blockDim.x + threadIdx.x;
    if (e >= E) return;
    int2 sd = g_edge2[e];
    float w = g_dinv[sd.x] * g_dinv[sd.y];
    int pos = atomicAdd(&g_cursor[sd.y], 1);
    g_csr[pos] = make_int2(sd.x, __float_as_int(w));
}

// ---------------- GEMM with fused pre-op (bias+relu of previous conv) ----------------
// C[n,FOUT] = preop(A)[n,FIN] @ W[FIN,FOUT] (+bias_out)
template<int FIN, int FOUT, bool PRE>
__global__ void k_gemm(const float* __restrict__ A, const float* __restrict__ W,
                       const float* __restrict__ bias_out,
                       const float* __restrict__ prebias,
                       float* __restrict__ C, int n) {
    __shared__ __align__(16) float Ws[FIN * FOUT];
    __shared__ __align__(16) float Pb[PRE ? FIN : 4];
    const int nthr = blockDim.x * blockDim.y;
    int tid = threadIdx.y * blockDim.x + threadIdx.x;
    for (int i = tid; i < FIN * FOUT / 4; i += nthr)
        ((float4*)Ws)[i] = ((const float4*)W)[i];
    if (PRE) {
        for (int i = tid; i < FIN; i += nthr) Pb[i] = prebias[i];
    }
    __syncthreads();

    const int tx = threadIdx.x;
    const int ty = threadIdx.y;
    const int row0 = blockIdx.x * 64 + ty * 4;

    const float4* A4  = (const float4*)A;
    const float4* Ws4 = (const float4*)Ws;

    int r[4];
#pragma unroll
    for (int i = 0; i < 4; i++) {
        int rr = row0 + i;
        r[i] = (rr < n) ? rr : (n - 1);
    }

    float acc[4][4] = {};
#pragma unroll 4
    for (int k4 = 0; k4 < FIN / 4; k4++) {
        float4 pb;
        if (PRE) pb = ((const float4*)Pb)[k4];
        float4 a[4];
#pragma unroll
        for (int i = 0; i < 4; i++) {
            a[i] = __ldg(A4 + (long)r[i] * (FIN / 4) + k4);
            if (PRE) {
                a[i].x = fmaxf(a[i].x + pb.x, 0.f);
                a[i].y = fmaxf(a[i].y + pb.y, 0.f);
                a[i].z = fmaxf(a[i].z + pb.z, 0.f);
                a[i].w = fmaxf(a[i].w + pb.w, 0.f);
            }
        }
#pragma unroll
        for (int kk = 0; kk < 4; kk++) {
            float4 w = Ws4[(k4 * 4 + kk) * (FOUT / 4) + tx];
#pragma unroll
            for (int i = 0; i < 4; i++) {
                float av = (kk == 0) ? a[i].x : (kk == 1) ? a[i].y : (kk == 2) ? a[i].z : a[i].w;
                acc[i][0] += av * w.x;
                acc[i][1] += av * w.y;
                acc[i][2] += av * w.z;
                acc[i][3] += av * w.w;
            }
        }
    }

    float4 bv = make_float4(0.f, 0.f, 0.f, 0.f);
    if (bias_out) bv = ((const float4*)bias_out)[tx];
#pragma unroll
    for (int i = 0; i < 4; i++) {
        int rr = row0 + i;
        if (rr < n) {
            float4 o = make_float4(acc[i][0] + bv.x, acc[i][1] + bv.y,
                                   acc[i][2] + bv.z, acc[i][3] + bv.w);
            ((float4*)C)[(long)rr * (FOUT / 4) + tx] = o;
        }
    }
}

// ---------------- CSR aggregation: out[v] = hW[v]*dinv^2 + sum_nbr hW[src]*w ----------------
// F/4 threads per node, each owns one float4 lane; registers accumulate.
// Edge record for iteration e+1 is prefetched while e's feature gather is in flight,
// breaking the record->gather serial dependency chain.
template<int F>
__global__ void k_agg(const float4* __restrict__ hw, float4* __restrict__ out, int n) {
    const int L = F / 4;
    int g = blockIdx.x * blockDim.x + threadIdx.x;
    int v = g / L;
    int l = g % L;
    if (v >= n) return;

    float s = g_dinv[v];
    float sw = s * s;
    float4 a = __ldg(hw + (long)v * L + l);
    float4 acc = make_float4(a.x * sw, a.y * sw, a.z * sw, a.w * sw);

    int st = g_rowstart[v];
    int cnt = g_deg[v] - 1;
    if (cnt > 0) {
        int2 rec = __ldg(&g_csr[st]);
        for (int e = st; e < st + cnt; e++) {
            int2 cur = rec;
            if (e + 1 < st + cnt) rec = __ldg(&g_csr[e + 1]);   // prefetch next record
            float w = __int_as_float(cur.y);
            float4 b = __ldg(hw + (long)cur.x * L + l);
            acc.x += b.x * w;
            acc.y += b.y * w;
            acc.z += b.z * w;
            acc.w += b.w * w;
        }
    }
    out[(long)v * L + l] = acc;
}

// ---------------- final: add bias, L2-normalize each 32-wide row ----------------
// Called with agg == out (in place); no __restrict__ on the aliased pair.
__global__ void k_final(const float* agg, const float* __restrict__ bias,
                        float* out, int n) {
    int gtid = blockIdx.x * blockDim.x + threadIdx.x;
    int row = gtid >> 5;
    int lane = gtid & 31;
    if (row >= n) return;
    float v = agg[(long)row * 32 + lane] + __ldg(&bias[lane]);
    float ss = v * v;
#pragma unroll
    for (int o = 16; o; o >>= 1) ss += __shfl_xor_sync(0xFFFFFFFFu, ss, o);
    float nrm = sqrtf(ss);
    out[(long)row * 32 + lane] = v / fmaxf(nrm, 1e-12f);
}

// ---------------- launch ----------------
extern "C" void kernel_launch(void* const* d_in, const int* in_sizes, int n_in,
                              void* d_out, int out_size) {
    const float* x    = (const float*)d_in[0];
    const void*  ei   = d_in[1];
    const float* Wpre = (const float*)d_in[2];
    const float* bpre = (const float*)d_in[3];
    const float* W1   = (const float*)d_in[4];
    const float* b1   = (const float*)d_in[5];
    const float* W2   = (const float*)d_in[6];
    const float* b2   = (const float*)d_in[7];
    const float* W3   = (const float*)d_in[8];
    const float* b3   = (const float*)d_in[9];

    int n = in_sizes[0] / 128;
    int E = in_sizes[1] / 2;

    float *buf0, *buf1, *buf2;
    cudaGetSymbolAddress((void**)&buf0, g_buf0);
    cudaGetSymbolAddress((void**)&buf1, g_buf1);
    cudaGetSymbolAddress((void**)&buf2, g_buf2);
    float* outp = (float*)d_out;

    const int T = 256;
    int nb_n  = (n + T - 1) / T;
    int nb_e  = (E + T - 1) / T;
    int nb_sc = (n + SCAN_TILE - 1) / SCAN_TILE;
    int nb_a64 = (n * 16 + T - 1) / T;   // n * (64/4) lanes
    int nb_a32 = (n * 8 + T - 1) / T;    // n * (32/4) lanes
    int nb_gem = (n + 63) / 64;

    // graph preprocessing: decode, degrees, norms, CSR build
    k_detect<<<1, 256>>>((const unsigned int*)ei);
    k_initdeg<<<nb_n, T>>>(n);
    k_edgeprep<<<nb_e, T>>>(ei, E, n);
    k_dinv<<<nb_n, T>>>(n);
    k_scan1<<<nb_sc, SCAN_TILE>>>(n);
    k_scan2<<<1, 128>>>(nb_sc);
    k_scan3<<<nb_n, T>>>(n);
    k_fill<<<nb_e, T>>>(E);

    // linear_pre: buf0 = x @ W_pre + b_pre
    k_gemm<128, 64, false><<<nb_gem, dim3(16, 16)>>>(x, Wpre, bpre, nullptr, buf0, n);

    // conv1: hW1 -> buf1; aggregate -> buf2 (bias+relu fused into next GEMM)
    k_gemm<64, 64, false><<<nb_gem, dim3(16, 16)>>>(buf0, W1, nullptr, nullptr, buf1, n);
    k_agg<64><<<nb_a64, T>>>((const float4*)buf1, (float4*)buf2, n);

    // conv2: reads agg1 with fused relu(+b1); hW2 -> buf0; aggregate -> buf1
    k_gemm<64, 64, true><<<nb_gem, dim3(16, 16)>>>(buf2, W2, nullptr, b1, buf0, n);
    k_agg<64><<<nb_a64, T>>>((const float4*)buf0, (float4*)buf1, n);

    // conv3: reads agg2 with fused relu(+b2); hW3 -> buf2; aggregate -> d_out
    k_gemm<64, 32, true><<<nb_gem, dim3(8, 16)>>>(buf1, W3, nullptr, b2, buf2, n);
    k_agg<32><<<nb_a32, T>>>((const float4*)buf2, (float4*)outp, n);

    // final: bias + L2 normalize, in place on d_out
    k_final<<<(n * 32 + T - 1) / T, T>>>(outp, b3, outp, n);
}